// round 3
// baseline (speedup 1.0000x reference)
#include <cuda_runtime.h>
#include <cstdint>

// Problem shape (fixed for this dataset entry; derived at runtime where possible):
//   features [B,N,8] f32, geometry [B,N,3] f32, W [C,8,8] f32, n_norm scalar (=N)
//   out [B,N,8] f32
static constexpr int   D        = 8;     // d_in = d_out
static constexpr int   A_TILE   = 128;   // a-points per CTA (one per thread)
static constexpr int   B_CHUNK  = 32;    // b-points staged in smem per CTA
static constexpr int   C_MAX    = 32;    // max radial basis count supported
static constexpr int   BN_MAX   = 2048;  // max B*N supported
static constexpr float R_MAX_F  = 3.5f;
static constexpr float EPS_F    = 1e-12f;
static constexpr float WIN      = 6.0f;  // Gaussian window: exp(-36) ~ 2e-16

// Scratch (static device arrays — no allocation allowed in kernel_launch)
__device__ float g_P[BN_MAX * C_MAX * D];                    // 2 MB: P[zb][c][i]
__device__ float g_partial[(BN_MAX / B_CHUNK) * BN_MAX * D]; // 4 MB: partial[split][a][i]

// n_norm may arrive as int32/int64 (python int) or float32. int32 view of a
// float32 >= 1.0 is >= 2^30, so a small positive int read means "integer".
__device__ __forceinline__ float decode_n(const void* p) {
    int iv = *(const int*)p;
    if (iv > 0 && iv < (1 << 30)) return (float)iv;
    return *(const float*)p;
}

// ---------------------------------------------------------------------------
// Kernel 1: P[zb,c,i] = (1/sqrt(n)) * sum_j W[c,i,j] * f[zb,j]
// ---------------------------------------------------------------------------
__global__ void precomp_P(const float* __restrict__ f,
                          const float* __restrict__ W,
                          const void* __restrict__ nptr,
                          int BN, int C) {
    int idx = blockIdx.x * blockDim.x + threadIdx.x;
    if (idx >= BN * C * D) return;
    int i  = idx & (D - 1);
    int t  = idx >> 3;           // zb*C + c
    int c  = t % C;
    int zb = t / C;
    float scale = rsqrtf(decode_n(nptr));
    const float* fr = f + (size_t)zb * D;
    const float* wr = W + ((size_t)c * D + i) * D;
    float s = 0.f;
#pragma unroll
    for (int j = 0; j < D; ++j) s = fmaf(wr[j], fr[j], s);
    g_P[idx] = s * scale;
}

// ---------------------------------------------------------------------------
// Kernel 2: partial[split][a][i] = sum_{b in chunk} sum_{c in window}
//                                   exp(-(t_ab - c)^2) * P[b][c][i]
// One thread per a; B_CHUNK b-points + their P rows staged in shared memory.
// ---------------------------------------------------------------------------
__global__ void __launch_bounds__(A_TILE)
conv_main(const float* __restrict__ geo, const void* __restrict__ nptr,
          int BN, int C) {
    const int N  = (int)decode_n(nptr);
    const int b0 = blockIdx.y * B_CHUNK;        // b offset within z
    if (b0 >= N) return;                        // inactive split (host over-provisions)
    const int nb  = min(B_CHUNK, N - b0);
    const int ag0 = blockIdx.x * A_TILE;        // global a start (tile within one z)
    const int z   = ag0 / N;
    const int bg0 = z * N + b0;                 // global b start

    __shared__ float4 Ps[B_CHUNK * C_MAX * 2];  // [b][c][2] float4 = P[b][c][0..7]
    __shared__ float  sgx[B_CHUNK], sgy[B_CHUNK], sgz[B_CHUNK];

    const int tid = threadIdx.x;
    {
        const float4* gp = (const float4*)(g_P + (size_t)bg0 * C * D);
        const int tot = nb * C * 2;
        for (int k = tid; k < tot; k += A_TILE) Ps[k] = gp[k];
        if (tid < nb) {
            const float* gb = geo + (size_t)(bg0 + tid) * 3;
            sgx[tid] = gb[0]; sgy[tid] = gb[1]; sgz[tid] = gb[2];
        }
    }
    __syncthreads();

    const int a = ag0 + tid;
    const float* ga = geo + (size_t)a * 3;
    const float gax = ga[0], gay = ga[1], gaz = ga[2];
    const float inv_w = (float)(C - 1) / R_MAX_F;   // t = d / width

    float4 acc0 = {0.f, 0.f, 0.f, 0.f};
    float4 acc1 = {0.f, 0.f, 0.f, 0.f};

    for (int bb = 0; bb < nb; ++bb) {
        const float dx = sgx[bb] - gax;
        const float dy = sgy[bb] - gay;
        const float dz = sgz[bb] - gaz;
        const float d2 = fmaf(dx, dx, fmaf(dy, dy, fmaf(dz, dz, EPS_F)));
        const float t  = sqrtf(d2) * inv_w;
        // Gaussian support window: outside |t-c| > 6 contributions < 2.3e-16
        const int cmin = max(0, (int)ceilf(t - WIN));
        const int cmax = min(C - 1, (int)(t + WIN));   // t+WIN > 0, trunc == floor
        const float4* pb = Ps + (size_t)bb * (C * 2);
        for (int c = cmin; c <= cmax; ++c) {
            const float u = t - (float)c;
            const float e = __expf(-u * u);
            const float4 p0 = pb[2 * c];
            const float4 p1 = pb[2 * c + 1];
            acc0.x = fmaf(e, p0.x, acc0.x);
            acc0.y = fmaf(e, p0.y, acc0.y);
            acc0.z = fmaf(e, p0.z, acc0.z);
            acc0.w = fmaf(e, p0.w, acc0.w);
            acc1.x = fmaf(e, p1.x, acc1.x);
            acc1.y = fmaf(e, p1.y, acc1.y);
            acc1.z = fmaf(e, p1.z, acc1.z);
            acc1.w = fmaf(e, p1.w, acc1.w);
        }
    }

    float4* op = (float4*)(g_partial + ((size_t)blockIdx.y * BN + a) * D);
    op[0] = acc0;
    op[1] = acc1;
}

// ---------------------------------------------------------------------------
// Kernel 3: out[a][i] = sum_splits partial[s][a][i]   (deterministic reduce)
// ---------------------------------------------------------------------------
__global__ void reduce_out(const void* __restrict__ nptr, int BN,
                           float* __restrict__ out) {
    int idx = blockIdx.x * blockDim.x + threadIdx.x;
    if (idx >= BN * D) return;
    const int N = (int)decode_n(nptr);
    const int S = (N + B_CHUNK - 1) / B_CHUNK;   // active splits
    float s = 0.f;
    for (int k = 0; k < S; ++k) s += g_partial[(size_t)k * BN * D + idx];
    out[idx] = s;
}

// ---------------------------------------------------------------------------
extern "C" void kernel_launch(void* const* d_in, const int* in_sizes, int n_in,
                              void* d_out, int out_size) {
    const float* f   = (const float*)d_in[0];   // features [B,N,8]
    const float* geo = (const float*)d_in[1];   // geometry [B,N,3]
    const float* W   = (const float*)d_in[2];   // W [C,8,8]
    const void*  nn  = d_in[3];                 // n_norm scalar
    float* out = (float*)d_out;

    const int BN = in_sizes[1] / 3;             // B*N
    const int C  = in_sizes[2] / (D * D);       // radial basis count

    // 1) P precompute
    {
        int threads = BN * C * D;
        precomp_P<<<(threads + 255) / 256, 256>>>(f, W, nn, BN, C);
    }
    // 2) Main contraction. grid.y over-provisions splits to BN/B_CHUNK since
    //    the host cannot separate B from N; inactive splits exit immediately.
    {
        dim3 grid(BN / A_TILE, BN / B_CHUNK);
        conv_main<<<grid, A_TILE>>>(geo, nn, BN, C);
    }
    // 3) Reduce partials into out
    {
        int threads = BN * D;
        reduce_out<<<(threads + 255) / 256, 256>>>(nn, BN, out);
    }
}

// round 4
// speedup vs baseline: 1.7031x; 1.7031x over previous
#include <cuda_runtime.h>
#include <cstdint>

// Problem shape: features [B,N,8] f32, geometry [B,N,3] f32, W [C,8,8] f32,
// n_norm scalar (=N), out [B,N,8] f32.
static constexpr int   D        = 8;     // d_in = d_out
static constexpr int   A_TILE   = 128;   // a-points per CTA (one per thread)
static constexpr int   B_CHUNK  = 16;    // b-points staged in smem per CTA
static constexpr int   C_MAX    = 32;    // max radial basis count supported
static constexpr int   BN_MAX   = 2048;  // max B*N supported
static constexpr float R_MAX_F  = 3.5f;
static constexpr float EPS_F    = 1e-12f;
// sqrt(log2(e)): fold the nat-exp -> exp2 conversion into the distance scale
static constexpr float SQRT_L2E = 1.20112240878644966f;

// Static scratch (no allocation allowed)
__device__ __align__(16) float g_P[BN_MAX * C_MAX * D];                    // 2 MB
__device__ __align__(16) float g_partial[(BN_MAX / B_CHUNK) * BN_MAX * D]; // 8 MB

// n_norm may arrive as int32/int64 (python int) or float32.
__device__ __forceinline__ float decode_n(const void* p) {
    int iv = *(const int*)p;
    if (iv > 0 && iv < (1 << 30)) return (float)iv;
    return *(const float*)p;
}

// ---------------------------------------------------------------------------
// Kernel 1: P[zb,c,i] = (1/sqrt(n)) * sum_j W[c,i,j] * f[zb,j]
// Thread per (zb, c): vectorized loads, 64 FMAs, coalesced 32B store.
// ---------------------------------------------------------------------------
__global__ void precomp_P(const float* __restrict__ f,
                          const float* __restrict__ W,
                          const void* __restrict__ nptr,
                          int BN, int C) {
    int idx = blockIdx.x * blockDim.x + threadIdx.x;
    if (idx >= BN * C) return;
    int c  = idx % C;
    int zb = idx / C;
    float scale = rsqrtf(decode_n(nptr));

    const float4* fr = (const float4*)(f + (size_t)zb * D);
    float4 f0 = __ldg(fr);
    float4 f1 = __ldg(fr + 1);
    const float4* wr = (const float4*)(W + (size_t)c * D * D);

    float o[D];
#pragma unroll
    for (int i = 0; i < D; ++i) {
        float4 w0 = __ldg(wr + 2 * i);
        float4 w1 = __ldg(wr + 2 * i + 1);
        float s = w0.x * f0.x;
        s = fmaf(w0.y, f0.y, s);
        s = fmaf(w0.z, f0.z, s);
        s = fmaf(w0.w, f0.w, s);
        s = fmaf(w1.x, f1.x, s);
        s = fmaf(w1.y, f1.y, s);
        s = fmaf(w1.z, f1.z, s);
        s = fmaf(w1.w, f1.w, s);
        o[i] = s * scale;
    }
    float4* op = (float4*)(g_P + (size_t)idx * D);   // (zb*C + c)*D
    op[0] = make_float4(o[0], o[1], o[2], o[3]);
    op[1] = make_float4(o[4], o[5], o[6], o[7]);
}

// ---------------------------------------------------------------------------
// Kernel 2: partial[split][a][i] = sum_{b in chunk} sum_{c=0..C-1}
//                                   exp(-(t_ab - c)^2) * P[b][c][i]
// c loop is warp-UNIFORM (no window): smem reads are broadcasts, and
// exp(-u^2) underflows to exact 0 outside the support, so no branching needed.
// D-accumulation uses packed f32x2 FMAs (FFMA2, PTX-only).
// ---------------------------------------------------------------------------
template <int CT>
__global__ void __launch_bounds__(A_TILE)
conv_main(const float* __restrict__ geo, const void* __restrict__ nptr,
          int BN, int Crt) {
    const int C  = (CT > 0) ? CT : Crt;
    const int N  = (int)decode_n(nptr);
    const int b0 = blockIdx.y * B_CHUNK;        // b offset within z
    if (b0 >= N) return;                        // inactive split
    const int nb  = min(B_CHUNK, N - b0);
    const int ag0 = blockIdx.x * A_TILE;        // global a start (tile within one z)
    const int z   = ag0 / N;
    const int bg0 = z * N + b0;                 // global b start

    __shared__ float4 Ps[B_CHUNK * C_MAX * 2];  // [bb][c][half] = P[b][c][0..7]
    __shared__ float  sgx[B_CHUNK], sgy[B_CHUNK], sgz[B_CHUNK];

    const int tid = threadIdx.x;
    {
        // Tile rows are contiguous in g_P -> straight vector copy.
        const float4* gp = (const float4*)(g_P + (size_t)bg0 * C * D);
        const int tot = nb * C * 2;
        for (int k = tid; k < tot; k += A_TILE) Ps[k] = gp[k];
        if (tid < nb) {
            const float* gb = geo + (size_t)(bg0 + tid) * 3;
            sgx[tid] = gb[0]; sgy[tid] = gb[1]; sgz[tid] = gb[2];
        }
    }
    __syncthreads();

    const int a = ag0 + tid;
    const float* ga = geo + (size_t)a * 3;
    const float gax = ga[0], gay = ga[1], gaz = ga[2];
    // t = d * (C-1)/R_MAX ; v = t*sqrt(log2e) so that 2^(-v^2) = e^(-u^2 * 1)
    const float kscale = ((float)(C - 1) / R_MAX_F) * SQRT_L2E;

    unsigned long long acc0 = 0ull, acc1 = 0ull, acc2 = 0ull, acc3 = 0ull;

    for (int bb = 0; bb < nb; ++bb) {
        const float dx = sgx[bb] - gax;
        const float dy = sgy[bb] - gay;
        const float dz = sgz[bb] - gaz;
        const float d2 = fmaf(dx, dx, fmaf(dy, dy, fmaf(dz, dz, EPS_F)));
        float dd;
        asm("sqrt.approx.f32 %0, %1;" : "=f"(dd) : "f"(d2));
        const float ts = dd * kscale;           // = t * sqrt(log2e)
        const ulonglong2* pb =
            (const ulonglong2*)(Ps + (size_t)bb * (C * 2));
#pragma unroll
        for (int c = 0; c < C; ++c) {
            // v = (t - c) * sqrt(log2e); constant c*SQRT_L2E folds at compile time
            const float v   = fmaf((float)c, -SQRT_L2E, ts);
            const float arg = -v * v;           // = -(u^2) * log2(e)
            float e;
            asm("ex2.approx.f32 %0, %1;" : "=f"(e) : "f"(arg)); // exp(-u^2)
            unsigned long long ee;
            asm("mov.b64 %0, {%1, %1};" : "=l"(ee) : "f"(e));   // pack (e,e)
            const ulonglong2 q0 = pb[2 * c];     // P[b][c][0..3]
            const ulonglong2 q1 = pb[2 * c + 1]; // P[b][c][4..7]
            asm("fma.rn.f32x2 %0, %1, %2, %0;" : "+l"(acc0) : "l"(q0.x), "l"(ee));
            asm("fma.rn.f32x2 %0, %1, %2, %0;" : "+l"(acc1) : "l"(q0.y), "l"(ee));
            asm("fma.rn.f32x2 %0, %1, %2, %0;" : "+l"(acc2) : "l"(q1.x), "l"(ee));
            asm("fma.rn.f32x2 %0, %1, %2, %0;" : "+l"(acc3) : "l"(q1.y), "l"(ee));
        }
    }

    const float2 r0 = *(const float2*)&acc0;
    const float2 r1 = *(const float2*)&acc1;
    const float2 r2 = *(const float2*)&acc2;
    const float2 r3 = *(const float2*)&acc3;
    float4* op = (float4*)(g_partial + ((size_t)blockIdx.y * BN + a) * D);
    op[0] = make_float4(r0.x, r0.y, r1.x, r1.y);
    op[1] = make_float4(r2.x, r2.y, r3.x, r3.y);
}

// ---------------------------------------------------------------------------
// Kernel 3: out[a][i] = sum_splits partial[s][a][i]   (deterministic reduce)
// ---------------------------------------------------------------------------
__global__ void reduce_out(const void* __restrict__ nptr, int BN,
                           float* __restrict__ out) {
    int idx = blockIdx.x * blockDim.x + threadIdx.x;
    if (idx >= BN * D) return;
    const int N = (int)decode_n(nptr);
    const int S = (N + B_CHUNK - 1) / B_CHUNK;   // active splits
    float s = 0.f;
    for (int k = 0; k < S; ++k) s += g_partial[(size_t)k * BN * D + idx];
    out[idx] = s;
}

// ---------------------------------------------------------------------------
extern "C" void kernel_launch(void* const* d_in, const int* in_sizes, int n_in,
                              void* d_out, int out_size) {
    const float* f   = (const float*)d_in[0];   // features [B,N,8]
    const float* geo = (const float*)d_in[1];   // geometry [B,N,3]
    const float* W   = (const float*)d_in[2];   // W [C,8,8]
    const void*  nn  = d_in[3];                 // n_norm scalar
    float* out = (float*)d_out;

    const int BN = in_sizes[1] / 3;             // B*N
    const int C  = in_sizes[2] / (D * D);       // radial basis count

    // 1) P precompute
    {
        int threads = BN * C;
        precomp_P<<<(threads + 255) / 256, 256>>>(f, W, nn, BN, C);
    }
    // 2) Main contraction. grid.y over-provisions splits to BN/B_CHUNK since
    //    the host cannot separate B from N; inactive splits exit immediately.
    {
        dim3 grid(BN / A_TILE, BN / B_CHUNK);
        if (C == 32)
            conv_main<32><<<grid, A_TILE>>>(geo, nn, BN, C);
        else
            conv_main<0><<<grid, A_TILE>>>(geo, nn, BN, C);
    }
    // 3) Reduce partials into out
    {
        int threads = BN * D;
        reduce_out<<<(threads + 255) / 256, 256>>>(nn, BN, out);
    }
}